// round 1
// baseline (speedup 1.0000x reference)
#include <cuda_runtime.h>

#define NN 512
#define TT 32
#define DD 1024
#define HH 1024
#define GG 4096   // 4*H
#define KK 3072   // H + H + D

// ---------------- scratch (device globals; no allocation allowed) -------------
__device__ float g_h[NN * HH];
__device__ float g_c[NN * HH];
__device__ float g_attn[NN * HH];
__device__ float g_v[(size_t)NN * GG];

typedef unsigned long long u64;

__device__ __forceinline__ u64 pack2(float lo, float hi) {
    u64 r;
    asm("mov.b64 %0, {%1, %2};" : "=l"(r) : "f"(lo), "f"(hi));
    return r;
}
__device__ __forceinline__ void unpack2(u64 v, float& lo, float& hi) {
    asm("mov.b64 {%0, %1}, %2;" : "=f"(lo), "=f"(hi) : "l"(v));
}
// packed fp32x2 FMA (Blackwell): d = a*b + d  (2 FMAs per instruction)
__device__ __forceinline__ void ffma2(u64& d, u64 a, u64 b) {
    asm("fma.rn.f32x2 %0, %1, %2, %0;" : "+l"(d) : "l"(a), "l"(b));
}

// ---------------- init: h0 = c0 = mean over the 16 spatial cells --------------
__global__ void init_kernel(const float* __restrict__ A) {
    int idx = blockIdx.x * 256 + threadIdx.x;        // idx = n*H + j
    const float4* a4 = (const float4*)(A + (size_t)idx * 16);
    float4 a0 = a4[0], a1 = a4[1], a2 = a4[2], a3 = a4[3];
    float s = ((a0.x + a0.y) + (a0.z + a0.w)) + ((a1.x + a1.y) + (a1.z + a1.w))
            + ((a2.x + a2.y) + (a2.z + a2.w)) + ((a3.x + a3.y) + (a3.z + a3.w));
    s *= (1.0f / 16.0f);
    g_h[idx] = s;
    g_c[idx] = s;
}

// ---------------- attention over 16 spatial cells ------------------------------
// scores[n,k] = sum_h h[n,h]*A[n,h,k] / 32 ; M = softmax_k ; attn[n,h] = sum_k A[n,h,k]*M[n,k]
__global__ void attn_kernel(const float* __restrict__ A) {
    int n = blockIdx.x;
    const float* Af = A + (size_t)n * HH * 16;
    const float* hp = g_h + (size_t)n * HH;

    float part[16];
#pragma unroll
    for (int k = 0; k < 16; ++k) part[k] = 0.0f;

    for (int j = threadIdx.x; j < HH; j += 256) {
        float hv = hp[j];
        const float4* a4 = (const float4*)(Af + (size_t)j * 16);
        float4 a;
        a = a4[0]; part[0]  += hv * a.x; part[1]  += hv * a.y; part[2]  += hv * a.z; part[3]  += hv * a.w;
        a = a4[1]; part[4]  += hv * a.x; part[5]  += hv * a.y; part[6]  += hv * a.z; part[7]  += hv * a.w;
        a = a4[2]; part[8]  += hv * a.x; part[9]  += hv * a.y; part[10] += hv * a.z; part[11] += hv * a.w;
        a = a4[3]; part[12] += hv * a.x; part[13] += hv * a.y; part[14] += hv * a.z; part[15] += hv * a.w;
    }
#pragma unroll
    for (int k = 0; k < 16; ++k)
#pragma unroll
        for (int off = 16; off; off >>= 1)
            part[k] += __shfl_xor_sync(0xffffffffu, part[k], off);

    __shared__ float sred[8][16];
    __shared__ float sM[16];
    int warp = threadIdx.x >> 5, lane = threadIdx.x & 31;
    if (lane == 0) {
#pragma unroll
        for (int k = 0; k < 16; ++k) sred[warp][k] = part[k];
    }
    __syncthreads();

    if (threadIdx.x < 32) {
        int k = lane & 15;
        float s = 0.0f;
#pragma unroll
        for (int w = 0; w < 8; ++w) s += sred[w][k];
        s *= (1.0f / 32.0f);                         // / sqrt(H)
        float m = s;
#pragma unroll
        for (int off = 8; off; off >>= 1) m = fmaxf(m, __shfl_xor_sync(0xffffffffu, m, off));
        float e = expf(s - m);
        float sum = e;
#pragma unroll
        for (int off = 8; off; off >>= 1) sum += __shfl_xor_sync(0xffffffffu, sum, off);
        if (lane < 16) sM[lane] = e / sum;
    }
    __syncthreads();

    float* ap = g_attn + (size_t)n * HH;
    for (int j = threadIdx.x; j < HH; j += 256) {
        const float4* a4 = (const float4*)(Af + (size_t)j * 16);
        float s = 0.0f;
        float4 a;
        a = a4[0]; s += a.x * sM[0]  + a.y * sM[1]  + a.z * sM[2]  + a.w * sM[3];
        a = a4[1]; s += a.x * sM[4]  + a.y * sM[5]  + a.z * sM[6]  + a.w * sM[7];
        a = a4[2]; s += a.x * sM[8]  + a.y * sM[9]  + a.z * sM[10] + a.w * sM[11];
        a = a4[3]; s += a.x * sM[12] + a.y * sM[13] + a.z * sM[14] + a.w * sM[15];
        ap[j] = s;
    }
}

// ---------------- fused gate GEMM: v = [h | attn | x_t] @ [Wh; Wattn; Wx] -----
// M=512, N=4096, K=3072. 128x128 tiles, BK=16, 256 threads, 8x8 per thread,
// packed f32x2 accumulators, double-buffered smem (1 sync / k-iter).
__device__ __forceinline__ const float* a_seg(int k0, const float* __restrict__ x,
                                              int t, long& stride) {
    if (k0 < 1024) { stride = HH; return g_h + k0; }
    if (k0 < 2048) { stride = HH; return g_attn + (k0 - 1024); }
    stride = (long)TT * DD;
    return x + (size_t)t * DD + (k0 - 2048);
}

__global__ __launch_bounds__(256, 1)
void gemm_kernel(const float* __restrict__ x, const float* __restrict__ Wx,
                 const float* __restrict__ Wh, const float* __restrict__ Wattn,
                 int t)
{
    __shared__ float As[2][16][128];   // transposed: As[k][m]
    __shared__ float Bs[2][16][128];   // Bs[k][n]

    const int tid = threadIdx.x;
    const int tx = tid & 15;
    const int ty = tid >> 4;
    const int m0 = blockIdx.y * 128;
    const int n0 = blockIdx.x * 128;

    // load coords: A -> row (tid>>1), 8 contiguous k at (tid&1)*8
    //              B -> row ty,       8 contiguous n at tx*8
    const int arow = tid >> 1;
    const int akq  = (tid & 1) * 8;
    const int brow = ty;
    const int bcol = tx * 8;

    u64 acc[8][4];
#pragma unroll
    for (int i = 0; i < 8; ++i)
#pragma unroll
        for (int j = 0; j < 4; ++j) acc[i][j] = 0ull;

    long astr;
    const float* Ab = a_seg(0, x, t, astr);
    const float* Bb = Wh;
    float4 a0r = *(const float4*)(Ab + (size_t)(m0 + arow) * astr + akq);
    float4 a1r = *(const float4*)(Ab + (size_t)(m0 + arow) * astr + akq + 4);
    float4 b0r = *(const float4*)(Bb + (size_t)brow * GG + n0 + bcol);
    float4 b1r = *(const float4*)(Bb + (size_t)brow * GG + n0 + bcol + 4);

    {
        As[0][akq + 0][arow] = a0r.x; As[0][akq + 1][arow] = a0r.y;
        As[0][akq + 2][arow] = a0r.z; As[0][akq + 3][arow] = a0r.w;
        As[0][akq + 4][arow] = a1r.x; As[0][akq + 5][arow] = a1r.y;
        As[0][akq + 6][arow] = a1r.z; As[0][akq + 7][arow] = a1r.w;
        *(float4*)&Bs[0][brow][bcol]     = b0r;
        *(float4*)&Bs[0][brow][bcol + 4] = b1r;
    }
    __syncthreads();

    const int NKT = KK / 16;   // 192
    for (int kt = 0; kt < NKT; ++kt) {
        int buf = kt & 1;

        if (kt < NKT - 1) {
            int k0 = (kt + 1) * 16;
            const float* Ab2 = a_seg(k0, x, t, astr);
            const float* Bb2 = (k0 < 1024) ? Wh + (size_t)k0 * GG
                             : (k0 < 2048) ? Wattn + (size_t)(k0 - 1024) * GG
                                           : Wx + (size_t)(k0 - 2048) * GG;
            a0r = *(const float4*)(Ab2 + (size_t)(m0 + arow) * astr + akq);
            a1r = *(const float4*)(Ab2 + (size_t)(m0 + arow) * astr + akq + 4);
            b0r = *(const float4*)(Bb2 + (size_t)brow * GG + n0 + bcol);
            b1r = *(const float4*)(Bb2 + (size_t)brow * GG + n0 + bcol + 4);
        }

#pragma unroll
        for (int kk = 0; kk < 16; ++kk) {
            float4 am0 = *(const float4*)&As[buf][kk][ty * 4];
            float4 am1 = *(const float4*)&As[buf][kk][ty * 4 + 64];
            float4 bn0 = *(const float4*)&Bs[buf][kk][tx * 4];
            float4 bn1 = *(const float4*)&Bs[buf][kk][tx * 4 + 64];
            u64 bp[4] = { pack2(bn0.x, bn0.y), pack2(bn0.z, bn0.w),
                          pack2(bn1.x, bn1.y), pack2(bn1.z, bn1.w) };
            float am[8] = { am0.x, am0.y, am0.z, am0.w,
                            am1.x, am1.y, am1.z, am1.w };
#pragma unroll
            for (int i = 0; i < 8; ++i) {
                u64 ap = pack2(am[i], am[i]);
#pragma unroll
                for (int j = 0; j < 4; ++j) ffma2(acc[i][j], ap, bp[j]);
            }
        }

        if (kt < NKT - 1) {
            int nb = buf ^ 1;
            As[nb][akq + 0][arow] = a0r.x; As[nb][akq + 1][arow] = a0r.y;
            As[nb][akq + 2][arow] = a0r.z; As[nb][akq + 3][arow] = a0r.w;
            As[nb][akq + 4][arow] = a1r.x; As[nb][akq + 5][arow] = a1r.y;
            As[nb][akq + 6][arow] = a1r.z; As[nb][akq + 7][arow] = a1r.w;
            *(float4*)&Bs[nb][brow][bcol]     = b0r;
            *(float4*)&Bs[nb][brow][bcol + 4] = b1r;
            __syncthreads();
        }
    }

    // epilogue: write v
#pragma unroll
    for (int i = 0; i < 8; ++i) {
        int row = m0 + ((i < 4) ? (ty * 4 + i) : (64 + ty * 4 + (i - 4)));
#pragma unroll
        for (int j = 0; j < 4; ++j) {
            int col = n0 + ((j < 2) ? (tx * 4 + 2 * j) : (64 + tx * 4 + 2 * (j - 2)));
            float lo, hi;
            unpack2(acc[i][j], lo, hi);
            *(float2*)&g_v[(size_t)row * GG + col] = make_float2(lo, hi);
        }
    }
}

// ---------------- gates + state update + output write --------------------------
__global__ void gate_kernel(const float* __restrict__ b, float* __restrict__ out, int t) {
    int idx = blockIdx.x * 256 + threadIdx.x;        // idx = n*H + j
    int n = idx >> 10;
    int j = idx & 1023;
    const float* vr = g_v + (size_t)n * GG;
    float vi = vr[j]        + b[j];
    float vf = vr[j + 1024] + b[j + 1024];
    float vo = vr[j + 2048] + b[j + 2048];
    float vg = vr[j + 3072] + b[j + 3072];
    float ig = 1.0f / (1.0f + expf(-vi));
    float fg = 1.0f / (1.0f + expf(-vf));
    float og = 1.0f / (1.0f + expf(-vo));
    float gg = tanhf(vg);
    float c = fg * g_c[idx] + ig * gg;
    float h = og * tanhf(c);
    g_c[idx] = c;
    g_h[idx] = h;
    out[(size_t)n * (TT * HH) + (size_t)t * HH + j] = h;
}

// ---------------- launch ---------------------------------------------------------
extern "C" void kernel_launch(void* const* d_in, const int* in_sizes, int n_in,
                              void* d_out, int out_size) {
    const float* x     = (const float*)d_in[0];   // (N, T, D)
    const float* A     = (const float*)d_in[1];   // (N, H, 4, 4)
    const float* Wx    = (const float*)d_in[2];   // (D, 4H)
    const float* Wh    = (const float*)d_in[3];   // (H, 4H)
    const float* Wattn = (const float*)d_in[4];   // (H, 4H)
    const float* b     = (const float*)d_in[5];   // (4H,)
    float* out = (float*)d_out;                   // (N, T, H)

    init_kernel<<<(NN * HH) / 256, 256>>>(A);
    for (int t = 0; t < TT; ++t) {
        attn_kernel<<<NN, 256>>>(A);
        gemm_kernel<<<dim3(GG / 128, 4), 256>>>(x, Wx, Wh, Wattn, t);
        gate_kernel<<<(NN * HH) / 256, 256>>>(b, out, t);
    }
}

// round 3
// speedup vs baseline: 2.5126x; 2.5126x over previous
#include <cuda_runtime.h>
#include <cuda_bf16.h>
#include <cstdint>

#define NN 512
#define TT 32
#define DD 1024
#define HH 1024
#define GG 4096   // 4*H
#define KK 3072   // H + H + D

// ---------------- scratch (device globals; no allocation allowed) -------------
__device__ float g_h[NN * HH];
__device__ float g_c[NN * HH];
__device__ float g_v[(size_t)NN * GG];
__device__ __align__(256) __nv_bfloat16 g_hhi[NN * HH], g_hlo[NN * HH];
__device__ __align__(256) __nv_bfloat16 g_ahi[NN * HH], g_alo[NN * HH];
__device__ __align__(256) __nv_bfloat16 g_xhi[(size_t)NN * TT * DD], g_xlo[(size_t)NN * TT * DD];
__device__ __align__(256) __nv_bfloat16 g_wthi[(size_t)GG * KK], g_wtlo[(size_t)GG * KK]; // W^T [4096][3072]

// ---------------- small helpers ------------------------------------------------
__device__ __forceinline__ uint32_t smem_u32(const void* p) {
    uint32_t a;
    asm("{ .reg .u64 t; cvta.to.shared.u64 t, %1; cvt.u32.u64 %0, t; }" : "=r"(a) : "l"(p));
    return a;
}
__device__ __forceinline__ void cp16(uint32_t dst, const void* src) {
    asm volatile("cp.async.cg.shared.global [%0], [%1], 16;" :: "r"(dst), "l"(src));
}
__device__ __forceinline__ void cp_commit() { asm volatile("cp.async.commit_group;" ::: "memory"); }
template <int N> __device__ __forceinline__ void cp_wait() {
    asm volatile("cp.async.wait_group %0;" :: "n"(N) : "memory");
}
__device__ __forceinline__ void split_bf16(float w, __nv_bfloat16& hi, __nv_bfloat16& lo) {
    hi = __float2bfloat16(w);
    lo = __float2bfloat16(w - __bfloat162float(hi));
}
__device__ __forceinline__ void ldsm4(uint32_t& r0, uint32_t& r1, uint32_t& r2, uint32_t& r3,
                                      uint32_t addr) {
    asm volatile("ldmatrix.sync.aligned.m8n8.x4.shared.b16 {%0,%1,%2,%3}, [%4];"
                 : "=r"(r0), "=r"(r1), "=r"(r2), "=r"(r3) : "r"(addr));
}
// D += A*B for m16n8k16 row.col bf16 -> f32
__device__ __forceinline__ void mma16816(float* d, const uint32_t* a, uint32_t b0, uint32_t b1) {
    asm volatile(
        "mma.sync.aligned.m16n8k16.row.col.f32.bf16.bf16.f32 "
        "{%0,%1,%2,%3}, {%4,%5,%6,%7}, {%8,%9}, {%0,%1,%2,%3};"
        : "+f"(d[0]), "+f"(d[1]), "+f"(d[2]), "+f"(d[3])
        : "r"(a[0]), "r"(a[1]), "r"(a[2]), "r"(a[3]), "r"(b0), "r"(b1));
}

// ---------------- one-time prep kernels ----------------------------------------
// Transpose + hi/lo split of [Wh; Wattn; Wx] (3072 x 4096) -> W^T (4096 x 3072) bf16
__global__ void prep_w(const float* __restrict__ Wx, const float* __restrict__ Wh,
                       const float* __restrict__ Wattn) {
    __shared__ float tile[32][33];
    int k0 = blockIdx.x * 32, n0 = blockIdx.y * 32;
#pragma unroll
    for (int dy = 0; dy < 32; dy += 8) {
        int k = k0 + threadIdx.y + dy;
        int n = n0 + threadIdx.x;
        const float* W;
        int kk = k;
        if (k < 1024)       { W = Wh; }
        else if (k < 2048)  { W = Wattn; kk = k - 1024; }
        else                { W = Wx;    kk = k - 2048; }
        tile[threadIdx.y + dy][threadIdx.x] = W[(size_t)kk * GG + n];
    }
    __syncthreads();
#pragma unroll
    for (int dy = 0; dy < 32; dy += 8) {
        int n = n0 + threadIdx.y + dy;
        int k = k0 + threadIdx.x;
        float w = tile[threadIdx.x][threadIdx.y + dy];
        __nv_bfloat16 hi, lo;
        split_bf16(w, hi, lo);
        g_wthi[(size_t)n * KK + k] = hi;
        g_wtlo[(size_t)n * KK + k] = lo;
    }
}

__global__ void prep_x(const float* __restrict__ x) {
    size_t i = (size_t)blockIdx.x * 256 + threadIdx.x;
    __nv_bfloat16 hi, lo;
    split_bf16(x[i], hi, lo);
    g_xhi[i] = hi;
    g_xlo[i] = lo;
}

// ---------------- init: h0 = c0 = mean over the 16 spatial cells ---------------
__global__ void init_kernel(const float* __restrict__ A) {
    int idx = blockIdx.x * 256 + threadIdx.x;
    const float4* a4 = (const float4*)(A + (size_t)idx * 16);
    float4 a0 = a4[0], a1 = a4[1], a2 = a4[2], a3 = a4[3];
    float s = ((a0.x + a0.y) + (a0.z + a0.w)) + ((a1.x + a1.y) + (a1.z + a1.w))
            + ((a2.x + a2.y) + (a2.z + a2.w)) + ((a3.x + a3.y) + (a3.z + a3.w));
    s *= (1.0f / 16.0f);
    g_h[idx] = s;
    g_c[idx] = s;
    __nv_bfloat16 hi, lo;
    split_bf16(s, hi, lo);
    g_hhi[idx] = hi;
    g_hlo[idx] = lo;
}

// ---------------- attention over 16 spatial cells ------------------------------
__global__ void attn_kernel(const float* __restrict__ A) {
    int n = blockIdx.x;
    const float* Af = A + (size_t)n * HH * 16;
    const float* hp = g_h + (size_t)n * HH;

    float part[16];
#pragma unroll
    for (int k = 0; k < 16; ++k) part[k] = 0.0f;

    for (int j = threadIdx.x; j < HH; j += 256) {
        float hv = hp[j];
        const float4* a4 = (const float4*)(Af + (size_t)j * 16);
        float4 a;
        a = a4[0]; part[0]  += hv * a.x; part[1]  += hv * a.y; part[2]  += hv * a.z; part[3]  += hv * a.w;
        a = a4[1]; part[4]  += hv * a.x; part[5]  += hv * a.y; part[6]  += hv * a.z; part[7]  += hv * a.w;
        a = a4[2]; part[8]  += hv * a.x; part[9]  += hv * a.y; part[10] += hv * a.z; part[11] += hv * a.w;
        a = a4[3]; part[12] += hv * a.x; part[13] += hv * a.y; part[14] += hv * a.z; part[15] += hv * a.w;
    }
#pragma unroll
    for (int k = 0; k < 16; ++k)
#pragma unroll
        for (int off = 16; off; off >>= 1)
            part[k] += __shfl_xor_sync(0xffffffffu, part[k], off);

    __shared__ float sred[8][16];
    __shared__ float sM[16];
    int warp = threadIdx.x >> 5, lane = threadIdx.x & 31;
    if (lane == 0) {
#pragma unroll
        for (int k = 0; k < 16; ++k) sred[warp][k] = part[k];
    }
    __syncthreads();

    if (threadIdx.x < 32) {
        int k = lane & 15;
        float s = 0.0f;
#pragma unroll
        for (int w = 0; w < 8; ++w) s += sred[w][k];
        s *= (1.0f / 32.0f);
        float m = s;
#pragma unroll
        for (int off = 8; off; off >>= 1) m = fmaxf(m, __shfl_xor_sync(0xffffffffu, m, off));
        float e = expf(s - m);
        float sum = e;
#pragma unroll
        for (int off = 8; off; off >>= 1) sum += __shfl_xor_sync(0xffffffffu, sum, off);
        if (lane < 16) sM[lane] = e / sum;
    }
    __syncthreads();

    for (int j = threadIdx.x; j < HH; j += 256) {
        const float4* a4 = (const float4*)(Af + (size_t)j * 16);
        float s = 0.0f;
        float4 a;
        a = a4[0]; s += a.x * sM[0]  + a.y * sM[1]  + a.z * sM[2]  + a.w * sM[3];
        a = a4[1]; s += a.x * sM[4]  + a.y * sM[5]  + a.z * sM[6]  + a.w * sM[7];
        a = a4[2]; s += a.x * sM[8]  + a.y * sM[9]  + a.z * sM[10] + a.w * sM[11];
        a = a4[3]; s += a.x * sM[12] + a.y * sM[13] + a.z * sM[14] + a.w * sM[15];
        size_t idx = (size_t)n * HH + j;
        __nv_bfloat16 hi, lo;
        split_bf16(s, hi, lo);
        g_ahi[idx] = hi;
        g_alo[idx] = lo;
    }
}

// ---------------- HMMA GEMM: v = [h | attn | x_t] @ [Wh; Wattn; Wx] -------------
// M=512, N=4096, K=3072; bf16x3 split precision via mma.sync m16n8k16.
// CTA tile 128x128, 8 warps (4m x 2n), warp tile 32x64. 3-stage cp.async pipeline.
#define STAGE_BYTES 65536
#define A_HI_OFF 0
#define A_LO_OFF 16384
#define B_HI_OFF 32768
#define B_LO_OFF 49152
#define GEMM_SMEM (3 * STAGE_BYTES)
#define NKT 48

__global__ __launch_bounds__(256, 1) void gemm_kernel(int t) {
    extern __shared__ char smem[];
    uint32_t sb = smem_u32(smem);
    const int tid = threadIdx.x;
    const int wid = tid >> 5;
    const int lane = tid & 31;
    const int wm = wid & 3;          // warp m index (0..3)
    const int wn = wid >> 2;         // warp n index (0..1)
    const int m0 = blockIdx.y * 128;
    const int n0 = blockIdx.x * 128;

    float acc[2][8][4];
#pragma unroll
    for (int i = 0; i < 2; ++i)
#pragma unroll
        for (int g = 0; g < 8; ++g)
#pragma unroll
            for (int r = 0; r < 4; ++r) acc[i][g][r] = 0.0f;

    // per-lane invariant ldmatrix offsets (within a split's 128x64-half tile)
    const uint32_t swb   = (lane & 7) << 4;
    const uint32_t aRow  = (uint32_t)(wm * 32 + (lane & 15)) * 128;   // +i*2048 for tile i
    const uint32_t aHalf = (uint32_t)(lane >> 4);                      // chunk parity
    const uint32_t bRow  = (uint32_t)(wn * 64 + (lane & 7) + ((lane >> 4) << 3)) * 128; // +p*2048
    const uint32_t bHalf = (uint32_t)((lane >> 3) & 1);

    auto load_tile = [&](int kt, int stage) {
        uint32_t base = sb + stage * STAGE_BYTES;
        const __nv_bfloat16 *ahi, *alo;
        size_t astr, akoff;
        if (kt < 16)      { ahi = g_hhi; alo = g_hlo; astr = HH; akoff = (size_t)kt * 64; }
        else if (kt < 32) { ahi = g_ahi; alo = g_alo; astr = HH; akoff = (size_t)(kt - 16) * 64; }
        else              { ahi = g_xhi; alo = g_xlo; astr = (size_t)TT * DD;
                            akoff = (size_t)t * DD + (size_t)(kt - 32) * 64; }
        size_t bkoff = (size_t)kt * 64;
#pragma unroll
        for (int i = 0; i < 4; ++i) {
            int c = tid + i * 256;
            int row = c >> 3, c16 = c & 7;
            uint32_t off = row * 128 + c16 * 16;
            uint32_t sw = off ^ ((off >> 3) & 0x70);
            size_t aoff = (size_t)(m0 + row) * astr + akoff + (size_t)c16 * 8;
            size_t boff = (size_t)(n0 + row) * KK + bkoff + (size_t)c16 * 8;
            cp16(base + A_HI_OFF + sw, ahi + aoff);
            cp16(base + A_LO_OFF + sw, alo + aoff);
            cp16(base + B_HI_OFF + sw, g_wthi + boff);
            cp16(base + B_LO_OFF + sw, g_wtlo + boff);
        }
    };

    load_tile(0, 0); cp_commit();
    load_tile(1, 1); cp_commit();

    for (int kt = 0; kt < NKT; ++kt) {
        cp_wait<1>();                 // stage kt resident
        __syncthreads();

        uint32_t base = sb + (kt % 3) * STAGE_BYTES;
        uint32_t ah_base = base + A_HI_OFF, al_base = base + A_LO_OFF;
        uint32_t bh_base = base + B_HI_OFF, bl_base = base + B_LO_OFF;

#pragma unroll
        for (int q = 0; q < 4; ++q) {
            uint32_t aChunk = ((2 * q + aHalf) << 4) ^ swb;
            uint32_t bChunk = ((2 * q + bHalf) << 4) ^ swb;

            uint32_t ahf[2][4], alf[2][4];
#pragma unroll
            for (int i = 0; i < 2; ++i) {
                uint32_t ao = aRow + (uint32_t)i * 2048 + aChunk;
                ldsm4(ahf[i][0], ahf[i][1], ahf[i][2], ahf[i][3], ah_base + ao);
                ldsm4(alf[i][0], alf[i][1], alf[i][2], alf[i][3], al_base + ao);
            }
            uint32_t bhf[4][4], blf[4][4];
#pragma unroll
            for (int p = 0; p < 4; ++p) {
                uint32_t bo = bRow + (uint32_t)p * 2048 + bChunk;
                ldsm4(bhf[p][0], bhf[p][1], bhf[p][2], bhf[p][3], bh_base + bo);
                ldsm4(blf[p][0], blf[p][1], blf[p][2], blf[p][3], bl_base + bo);
            }
#pragma unroll
            for (int i = 0; i < 2; ++i)
#pragma unroll
                for (int g = 0; g < 8; ++g) {
                    uint32_t b0h = bhf[g >> 1][(g & 1) * 2], b1h = bhf[g >> 1][(g & 1) * 2 + 1];
                    uint32_t b0l = blf[g >> 1][(g & 1) * 2], b1l = blf[g >> 1][(g & 1) * 2 + 1];
                    mma16816(acc[i][g], ahf[i], b0h, b1h);   // hi*hi
                    mma16816(acc[i][g], ahf[i], b0l, b1l);   // hi*lo
                    mma16816(acc[i][g], alf[i], b0h, b1h);   // lo*hi
                }
        }

        __syncthreads();
        if (kt + 2 < NKT) load_tile(kt + 2, (kt + 2) % 3);
        cp_commit();
    }

    // epilogue: direct float2 stores
#pragma unroll
    for (int i = 0; i < 2; ++i) {
        int row0 = m0 + wm * 32 + i * 16 + (lane >> 2);
#pragma unroll
        for (int g = 0; g < 8; ++g) {
            int col = n0 + wn * 64 + g * 8 + (lane & 3) * 2;
            *(float2*)&g_v[(size_t)row0 * GG + col]       = make_float2(acc[i][g][0], acc[i][g][1]);
            *(float2*)&g_v[(size_t)(row0 + 8) * GG + col] = make_float2(acc[i][g][2], acc[i][g][3]);
        }
    }
}

// ---------------- gates + state update + output write --------------------------
__global__ void gate_kernel(const float* __restrict__ b, float* __restrict__ out, int t) {
    int idx = blockIdx.x * 256 + threadIdx.x;
    int n = idx >> 10;
    int j = idx & 1023;
    const float* vr = g_v + (size_t)n * GG;
    float vi = vr[j]        + b[j];
    float vf = vr[j + 1024] + b[j + 1024];
    float vo = vr[j + 2048] + b[j + 2048];
    float vg = vr[j + 3072] + b[j + 3072];
    float ig = 1.0f / (1.0f + expf(-vi));
    float fg = 1.0f / (1.0f + expf(-vf));
    float og = 1.0f / (1.0f + expf(-vo));
    float gg = tanhf(vg);
    float c = fg * g_c[idx] + ig * gg;
    float h = og * tanhf(c);
    g_c[idx] = c;
    g_h[idx] = h;
    __nv_bfloat16 hi, lo;
    split_bf16(h, hi, lo);
    g_hhi[idx] = hi;
    g_hlo[idx] = lo;
    out[(size_t)n * (TT * HH) + (size_t)t * HH + j] = h;
}

// ---------------- launch ---------------------------------------------------------
extern "C" void kernel_launch(void* const* d_in, const int* in_sizes, int n_in,
                              void* d_out, int out_size) {
    const float* x     = (const float*)d_in[0];   // (N, T, D)
    const float* A     = (const float*)d_in[1];   // (N, H, 4, 4)
    const float* Wx    = (const float*)d_in[2];   // (D, 4H)
    const float* Wh    = (const float*)d_in[3];   // (H, 4H)
    const float* Wattn = (const float*)d_in[4];   // (H, 4H)
    const float* b     = (const float*)d_in[5];   // (4H,)
    float* out = (float*)d_out;                   // (N, T, H)

    cudaFuncSetAttribute(gemm_kernel, cudaFuncAttributeMaxDynamicSharedMemorySize, GEMM_SMEM);

    prep_w<<<dim3(KK / 32, GG / 32), dim3(32, 8)>>>(Wx, Wh, Wattn);
    prep_x<<<(NN * TT * DD) / 256, 256>>>(x);
    init_kernel<<<(NN * HH) / 256, 256>>>(A);
    for (int t = 0; t < TT; ++t) {
        attn_kernel<<<NN, 256>>>(A);
        gemm_kernel<<<dim3(GG / 128, NN / 128), 256, GEMM_SMEM>>>(t);
        gate_kernel<<<(NN * HH) / 256, 256>>>(b, out, t);
    }
}